// round 15
// baseline (speedup 1.0000x reference)
#include <cuda_runtime.h>
#include <cstdint>

// Problem shape (fixed by reference)
#define T_DIM 16384
#define B_DIM 64
#define E_DIM 4096

#define NCHUNK     4
#define CHUNK_T    (T_DIM / NCHUNK)     // 4096 rows per chunk
#define SCAN_THR   256                  // scan threads per chunk (16 elems each)

// Permuted scratch layout (coalesced scan):
//   PERM(t) = (t & 15) * 1024 + (t >> 4)
// Scan thread tid of chunk c owns t = c*4096 + 16*tid + i  ->  addr i*1024 + c*256 + tid
__device__ __forceinline__ int PERM(int t) { return ((t & 15) << 10) | (t >> 4); }

// Scratch (allocation-free). Packed float2: (.x=alpha/A, .y=beta/B)
__device__ float2 g_ab[T_DIM];
__device__ float2 g_AB[T_DIM];
__device__ float2 g_carry;   // inclusive (A,B) at end of previous chunk

// ---------------------------------------------------------------------------
// Gather + reduce for one chunk of 4096 t-rows. 2 rows/warp, 512-thr blocks.
// (L1tex wavefront floor: ~2.4us/chunk, occupancy-invariant.)
// ---------------------------------------------------------------------------
__global__ void __launch_bounds__(512) gather_chunk_kernel(
        const int* __restrict__ indices, const float* __restrict__ params,
        int t_base) {
    int gwarp = (blockIdx.x * blockDim.x + threadIdx.x) >> 5;
    int lane  = threadIdx.x & 31;
    int t0 = t_base + gwarp * 2;

    const float2* p2 = (const float2*)params;

    int2 i0 = ((const int2*)(indices + (size_t)t0       * B_DIM))[lane];
    int2 i1 = ((const int2*)(indices + (size_t)(t0 + 1) * B_DIM))[lane];
    float2 a0 = __ldg(&p2[i0.x]);
    float2 b0 = __ldg(&p2[i0.y]);
    float2 a1 = __ldg(&p2[i1.x]);
    float2 b1 = __ldg(&p2[i1.y]);

    float s0a = a0.x + b0.x, s0b = a0.y + b0.y;
    float s1a = a1.x + b1.x, s1b = a1.y + b1.y;
    #pragma unroll
    for (int off = 16; off > 0; off >>= 1) {
        s0a += __shfl_xor_sync(0xFFFFFFFFu, s0a, off);
        s0b += __shfl_xor_sync(0xFFFFFFFFu, s0b, off);
        s1a += __shfl_xor_sync(0xFFFFFFFFu, s1a, off);
        s1b += __shfl_xor_sync(0xFFFFFFFFu, s1b, off);
    }
    if (lane == 0) {
        g_ab[PERM(t0)]     = make_float2(s0a, s0b);
        g_ab[PERM(t0 + 1)] = make_float2(s1a, s1b);
    }
}

// ---------------------------------------------------------------------------
// Scan one chunk of 4096 elements (256 threads x 16), chaining carry through
// g_carry (chunk 0 uses identity and never reads it -> replay-deterministic).
// Compose (ordered): compose(earlier=(A,B), later=(a,b)) = (a*A, a*B + b)
// ---------------------------------------------------------------------------
__global__ void __launch_bounds__(SCAN_THR) scan_chunk_kernel(int chunk) {
    __shared__ float2 sW[8];    // per-warp inclusive totals

    const int tid  = threadIdx.x;
    const int lane = tid & 31;
    const int wid  = tid >> 5;
    const int col  = chunk * SCAN_THR + tid;   // permuted column

    float2 e[16];
    #pragma unroll
    for (int i = 0; i < 16; i++) e[i] = g_ab[i * 1024 + col];

    // carry-in (inclusive total of all earlier chunks)
    float cpa = 1.0f, cpb = 0.0f;
    if (chunk > 0) { float2 c = g_carry; cpa = c.x; cpb = c.y; }

    // thread-local inclusive aggregate (in order)
    float ca = 1.0f, cb = 0.0f;
    #pragma unroll
    for (int i = 0; i < 16; i++) {
        cb = fmaf(e[i].x, cb, e[i].y);
        ca = e[i].x * ca;
    }

    // warp inclusive scan: new = compose(lower=(pa,pb), mine=(wa,wb))
    float wa = ca, wb = cb;
    #pragma unroll
    for (int off = 1; off < 32; off <<= 1) {
        float pa = __shfl_up_sync(0xFFFFFFFFu, wa, off);
        float pb = __shfl_up_sync(0xFFFFFFFFu, wb, off);
        float na = (lane >= off) ? wa * pa          : wa;
        float nb = (lane >= off) ? fmaf(wa, pb, wb) : wb;
        wa = na; wb = nb;
    }
    if (lane == 31) sW[wid] = make_float2(wa, wb);
    __syncthreads();

    // warp 0: inclusive scan of the 8 warp totals (lanes 0..7)
    if (wid == 0) {
        float xa = (lane < 8) ? sW[lane].x : 1.0f;
        float xb = (lane < 8) ? sW[lane].y : 0.0f;
        #pragma unroll
        for (int off = 1; off < 8; off <<= 1) {
            float pa = __shfl_up_sync(0xFFFFFFFFu, xa, off);
            float pb = __shfl_up_sync(0xFFFFFFFFu, xb, off);
            float na = (lane >= off) ? xa * pa          : xa;
            float nb = (lane >= off) ? fmaf(xa, pb, xb) : xb;
            xa = na; xb = nb;
        }
        if (lane < 8) sW[lane] = make_float2(xa, xb);
    }
    __syncthreads();

    // carry-out = compose(carry_in, block_total=sW[7])   (thread 0)
    if (tid == 0) {
        float2 bt = sW[7];
        g_carry = make_float2(bt.x * cpa, fmaf(bt.x, cpb, bt.y));
    }

    // exclusive prefix = compose(carry_in, compose(warp_prefix, lane_excl))
    float wpa = (wid > 0) ? sW[wid - 1].x : 1.0f;
    float wpb = (wid > 0) ? sW[wid - 1].y : 0.0f;
    float lea = __shfl_up_sync(0xFFFFFFFFu, wa, 1);
    float leb = __shfl_up_sync(0xFFFFFFFFu, wb, 1);
    if (lane == 0) { lea = 1.0f; leb = 0.0f; }
    // block-exclusive
    float bea = lea * wpa;
    float beb = fmaf(lea, wpb, leb);
    // with carry
    float pa = bea * cpa;
    float pb = fmaf(bea, cpb, beb);

    // replay local elements applying prefix; coalesced permuted writes
    #pragma unroll
    for (int i = 0; i < 16; i++) {
        pb = fmaf(e[i].x, pb, e[i].y);
        pa = e[i].x * pa;
        g_AB[i * 1024 + col] = make_float2(pa, pb);
    }
}

// ---------------------------------------------------------------------------
// Broadcast store for one chunk: out[t, e] = A[t]*M_prev[e] + B[t].
// Block = E-chunk (1024 floats) x 16 t-rows; __stcs streaming stores.
// ---------------------------------------------------------------------------
#define K3_ROWS 16
__global__ void __launch_bounds__(256) broadcast_chunk_kernel(
        const float* __restrict__ M_prev, float* __restrict__ out, int t_base) {
    __shared__ float2 sAB[K3_ROWS];

    const int t0  = t_base + blockIdx.y * K3_ROWS;  // multiple of 16
    const int grp = t0 >> 4;                        // PERM(t0+r) = r*1024 + grp
    if (threadIdx.x < K3_ROWS) {
        sAB[threadIdx.x] = g_AB[threadIdx.x * 1024 + grp];
    }

    const int col = blockIdx.x * 256 + threadIdx.x; // float4 column index
    float4 m = __ldg(&((const float4*)M_prev)[col]);
    __syncthreads();

    float4* o4 = (float4*)out;
    #pragma unroll
    for (int r = 0; r < K3_ROWS; r++) {
        float a = sAB[r].x;
        float b = sAB[r].y;
        float4 v;
        v.x = fmaf(a, m.x, b);
        v.y = fmaf(a, m.y, b);
        v.z = fmaf(a, m.z, b);
        v.w = fmaf(a, m.w, b);
        __stcs(&o4[(size_t)(t0 + r) * (E_DIM / 4) + col], v);
    }
}

// ---------------------------------------------------------------------------
// Graph-level pipeline: chunk-0 gather on the capture stream; chunks 1..3
// gathers on a forked non-blocking stream (event fork/join, the documented
// capture pattern) so they overlap the preceding chunks' store kernels.
// Stream/events are host objects created once (no device memory); the
// captured work is identical on every call.
// ---------------------------------------------------------------------------
extern "C" void kernel_launch(void* const* d_in, const int* in_sizes, int n_in,
                              void* d_out, int out_size) {
    const int*   indices = (const int*)d_in[0];   // (T, B) int32 (JAX downcast)
    const float* M_prev  = (const float*)d_in[1]; // (E,)   f32
    const float* params  = (const float*)d_in[2]; // (N, 2) f32
    float*       out     = (float*)d_out;         // (T, E) f32

    static cudaStream_t s1 = nullptr;
    static cudaEvent_t  evFork = nullptr;
    static cudaEvent_t  evG[NCHUNK];
    if (s1 == nullptr) {
        cudaStreamCreateWithFlags(&s1, cudaStreamNonBlocking);
        cudaEventCreateWithFlags(&evFork, cudaEventDisableTiming);
        for (int c = 1; c < NCHUNK; c++)
            cudaEventCreateWithFlags(&evG[c], cudaEventDisableTiming);
    }

    const int g1_blocks = (CHUNK_T / 2 * 32) / 512;          // 128
    dim3 g3(E_DIM / (256 * 4), CHUNK_T / K3_ROWS);           // (4, 256)

    // chunk 0 gather on the capture (legacy) stream
    gather_chunk_kernel<<<g1_blocks, 512>>>(indices, params, 0);

    // fork: gathers for chunks 1..3 on s1, each tagged with an event
    cudaEventRecord(evFork, 0);
    cudaStreamWaitEvent(s1, evFork, 0);
    for (int c = 1; c < NCHUNK; c++) {
        gather_chunk_kernel<<<g1_blocks, 512, 0, s1>>>(indices, params, c * CHUNK_T);
        cudaEventRecord(evG[c], s1);
    }

    // chunk 0 scan + store
    scan_chunk_kernel<<<1, SCAN_THR>>>(0);
    broadcast_chunk_kernel<<<g3, 256>>>(M_prev, out, 0);

    // chunks 1..3: join on that chunk's gather, then scan + store
    for (int c = 1; c < NCHUNK; c++) {
        cudaStreamWaitEvent(0, evG[c], 0);
        scan_chunk_kernel<<<1, SCAN_THR>>>(c);
        broadcast_chunk_kernel<<<g3, 256>>>(M_prev, out, c * CHUNK_T);
    }
}

// round 16
// speedup vs baseline: 1.1504x; 1.1504x over previous
#include <cuda_runtime.h>
#include <cstdint>

// Problem shape (fixed by reference)
#define T_DIM 16384
#define B_DIM 64
#define E_DIM 4096

// Permuted scratch layout so the single-block scan kernel is fully coalesced:
//   P(t) = (t & 15) * 1024 + (t >> 4)
// Scan thread `tid` owns t = 16*tid + i (i=0..15) -> permuted addr i*1024+tid
// -> every warp access is one coalesced transaction.
__device__ __forceinline__ int PERM(int t) { return ((t & 15) << 10) | (t >> 4); }

// Scratch (allocation-free). Packed float2: (.x=alpha/A, .y=beta/B)
__device__ float2 g_ab[T_DIM];
__device__ float2 g_AB[T_DIM];

// ---------------------------------------------------------------------------
// Kernel 1: per-t gather + reduce over B=64.
// At the L1tex wavefront floor for ~1M random 8B gathers (~9.3us,
// occupancy-invariant, verified R6-R9/R14). 2 rows/warp, 512-thr blocks.
// ---------------------------------------------------------------------------
#define K1_ROWS 2
__global__ void __launch_bounds__(512) gather_reduce_kernel(
        const int* __restrict__ indices, const float* __restrict__ params) {
    int gwarp = (blockIdx.x * blockDim.x + threadIdx.x) >> 5;
    int lane  = threadIdx.x & 31;
    int t0 = gwarp * K1_ROWS;

    const float2* p2 = (const float2*)params;

    int2 idx[K1_ROWS];
    #pragma unroll
    for (int r = 0; r < K1_ROWS; r++) {
        idx[r] = ((const int2*)(indices + (size_t)(t0 + r) * B_DIM))[lane];
    }

    float2 v0[K1_ROWS], v1[K1_ROWS];
    #pragma unroll
    for (int r = 0; r < K1_ROWS; r++) v0[r] = __ldg(&p2[idx[r].x]);
    #pragma unroll
    for (int r = 0; r < K1_ROWS; r++) v1[r] = __ldg(&p2[idx[r].y]);

    #pragma unroll
    for (int r = 0; r < K1_ROWS; r++) {
        float sa = v0[r].x + v1[r].x;
        float sb = v0[r].y + v1[r].y;
        #pragma unroll
        for (int off = 16; off > 0; off >>= 1) {
            sa += __shfl_xor_sync(0xFFFFFFFFu, sa, off);
            sb += __shfl_xor_sync(0xFFFFFFFFu, sb, off);
        }
        if (lane == 0) {
            g_ab[PERM(t0 + r)] = make_float2(sa, sb);
        }
    }
}

// ---------------------------------------------------------------------------
// Kernel 2: linear-recurrence scan over T=16384.
// Single block, 1024 threads, 16 elements/thread, shuffle-based block scan.
// Compose (ordered): compose(earlier=(A,B), later=(a,b)) = (a*A, a*B + b)
// ---------------------------------------------------------------------------
__global__ void __launch_bounds__(1024) scan_kernel() {
    __shared__ float2 sW[32];   // per-warp inclusive totals

    const int tid  = threadIdx.x;
    const int lane = tid & 31;
    const int wid  = tid >> 5;

    float2 e[16];
    #pragma unroll
    for (int i = 0; i < 16; i++) e[i] = g_ab[i * 1024 + tid];

    // thread-local inclusive aggregate (in order)
    float ca = 1.0f, cb = 0.0f;
    #pragma unroll
    for (int i = 0; i < 16; i++) {
        cb = fmaf(e[i].x, cb, e[i].y);
        ca = e[i].x * ca;
    }

    // warp inclusive scan over thread aggregates:
    // new = compose(prev_from_lower=(pa,pb), mine=(wa,wb)) = (wa*pa, wa*pb+wb)
    float wa = ca, wb = cb;
    #pragma unroll
    for (int off = 1; off < 32; off <<= 1) {
        float pa = __shfl_up_sync(0xFFFFFFFFu, wa, off);
        float pb = __shfl_up_sync(0xFFFFFFFFu, wb, off);
        float na = (lane >= off) ? wa * pa          : wa;
        float nb = (lane >= off) ? fmaf(wa, pb, wb) : wb;
        wa = na; wb = nb;
    }

    if (lane == 31) sW[wid] = make_float2(wa, wb);
    __syncthreads();

    // warp 0 scans the 32 warp totals (inclusive)
    if (wid == 0) {
        float xa = sW[lane].x, xb = sW[lane].y;
        #pragma unroll
        for (int off = 1; off < 32; off <<= 1) {
            float pa = __shfl_up_sync(0xFFFFFFFFu, xa, off);
            float pb = __shfl_up_sync(0xFFFFFFFFu, xb, off);
            float na = (lane >= off) ? xa * pa          : xa;
            float nb = (lane >= off) ? fmaf(xa, pb, xb) : xb;
            xa = na; xb = nb;
        }
        sW[lane] = make_float2(xa, xb);
    }
    __syncthreads();

    // block-exclusive prefix = compose(warp_prefix, lane_exclusive)
    float wpa = (wid > 0) ? sW[wid - 1].x : 1.0f;
    float wpb = (wid > 0) ? sW[wid - 1].y : 0.0f;
    float lea = __shfl_up_sync(0xFFFFFFFFu, wa, 1);
    float leb = __shfl_up_sync(0xFFFFFFFFu, wb, 1);
    if (lane == 0) { lea = 1.0f; leb = 0.0f; }
    float pa = lea * wpa;
    float pb = fmaf(lea, wpb, leb);

    // replay local elements applying prefix; coalesced permuted writes
    #pragma unroll
    for (int i = 0; i < 16; i++) {
        pb = fmaf(e[i].x, pb, e[i].y);
        pa = e[i].x * pa;
        g_AB[i * 1024 + tid] = make_float2(pa, pb);
    }
}

// ---------------------------------------------------------------------------
// Kernel 3: output broadcast.  out[t, e] = A[t] * M_prev[e] + B[t]
// Block = one E-chunk (1024 floats as float4) x 16 t-rows; A/B staged to
// shared; 16 independent STG.128 streams/thread with __stcs (write-once
// output, 2x L2 capacity). Measured at ~6.9 TB/s — the HBM write ceiling.
// ---------------------------------------------------------------------------
#define K3_ROWS   16
#define K3_CHUNKS (E_DIM / (256 * 4))   // 4 column chunks of 1024 floats

__global__ void __launch_bounds__(256) broadcast_kernel(
        const float* __restrict__ M_prev, float* __restrict__ out) {
    __shared__ float2 sAB[K3_ROWS];

    const int t0  = blockIdx.y * K3_ROWS;   // multiple of 16
    const int grp = t0 >> 4;                // PERM(t0+r) = r*1024 + grp
    if (threadIdx.x < K3_ROWS) {
        sAB[threadIdx.x] = g_AB[threadIdx.x * 1024 + grp];
    }

    const int col = blockIdx.x * 256 + threadIdx.x;   // float4 column index
    float4 m = __ldg(&((const float4*)M_prev)[col]);
    __syncthreads();

    float4* o4 = (float4*)out;
    #pragma unroll
    for (int r = 0; r < K3_ROWS; r++) {
        float a = sAB[r].x;
        float b = sAB[r].y;
        float4 v;
        v.x = fmaf(a, m.x, b);
        v.y = fmaf(a, m.y, b);
        v.z = fmaf(a, m.z, b);
        v.w = fmaf(a, m.w, b);
        __stcs(&o4[(size_t)(t0 + r) * (E_DIM / 4) + col], v);
    }
}

// ---------------------------------------------------------------------------
extern "C" void kernel_launch(void* const* d_in, const int* in_sizes, int n_in,
                              void* d_out, int out_size) {
    const int*   indices = (const int*)d_in[0];   // (T, B) int32 (JAX downcast)
    const float* M_prev  = (const float*)d_in[1]; // (E,)   f32
    const float* params  = (const float*)d_in[2]; // (N, 2) f32
    float*       out     = (float*)d_out;         // (T, E) f32

    // K1: 8192 warps (2 rows each), 512-thread blocks
    gather_reduce_kernel<<<T_DIM / K1_ROWS * 32 / 512, 512>>>(indices, params);

    // K2: single-block shuffle scan
    scan_kernel<<<1, 1024>>>();

    // K3: (4 column chunks) x (1024 row groups)
    dim3 g3(K3_CHUNKS, T_DIM / K3_ROWS);
    broadcast_kernel<<<g3, 256>>>(M_prev, out);
}